// round 13
// baseline (speedup 1.0000x reference)
#include <cuda_runtime.h>
#include <cuda_bf16.h>
#include <cstdint>

// Problem constants (fixed by the dataset)
#define NTOT    80000      // B * NF
#define NFINE   20000
#define NBATCH  4
#define NCOARSE 2000
#define HDIM    512
#define DEGCAP  32         // padded CSR slot size (in-degree ~ Poisson(6))

// ----------------------------------------------------------------------------
// Scratch (device globals; no allocations allowed)
// ----------------------------------------------------------------------------
__device__ __nv_bfloat16 g_HaHi[(size_t)NTOT * HDIM];
__device__ __nv_bfloat16 g_HaLo[(size_t)NTOT * HDIM];
__device__ __nv_bfloat16 g_HbHi[(size_t)NTOT * HDIM];
__device__ __nv_bfloat16 g_HbLo[(size_t)NTOT * HDIM];
__device__ float g_T [(size_t)NTOT * HDIM];
__device__ __nv_bfloat16 g_WThi[4 * HDIM * HDIM];  // transposed weights [slot][n][k]
__device__ __nv_bfloat16 g_WTlo[4 * HDIM * HDIM];
__device__ float g_y3[(size_t)NTOT * 3];
__device__ float g_t3[(size_t)NTOT * 3];
__device__ float g_dinv[NTOT];
__device__ int   g_cnt[NTOT];
__device__ int   g_cur[NTOT];
__device__ int2  g_edgeP[(size_t)NTOT * DEGCAP];   // padded: {src, bitcast(w)}

// ----------------------------------------------------------------------------
// Warp MMA helpers (plain sm_100-compatible PTX: ldmatrix / mma.sync / cp.async)
// ----------------------------------------------------------------------------
__device__ __forceinline__ uint32_t smem_u32(const void* p) {
    uint32_t a;
    asm("{ .reg .u64 t; cvta.to.shared.u64 t, %1; cvt.u32.u64 %0, t; }"
        : "=r"(a) : "l"(p));
    return a;
}
__device__ __forceinline__ void ldsm4(uint32_t* d, uint32_t addr) {
    asm volatile("ldmatrix.sync.aligned.m8n8.x4.shared.b16 {%0,%1,%2,%3}, [%4];"
        : "=r"(d[0]), "=r"(d[1]), "=r"(d[2]), "=r"(d[3]) : "r"(addr));
}
__device__ __forceinline__ void mma16816(float* c, const uint32_t* a,
                                         uint32_t b0, uint32_t b1) {
    asm volatile(
        "mma.sync.aligned.m16n8k16.row.col.f32.bf16.bf16.f32 "
        "{%0,%1,%2,%3}, {%4,%5,%6,%7}, {%8,%9}, {%0,%1,%2,%3};"
        : "+f"(c[0]), "+f"(c[1]), "+f"(c[2]), "+f"(c[3])
        : "r"(a[0]), "r"(a[1]), "r"(a[2]), "r"(a[3]), "r"(b0), "r"(b1));
}
__device__ __forceinline__ void cp_async16(uint32_t dst, const void* src) {
    asm volatile("cp.async.cg.shared.global [%0], [%1], 16;"
        :: "r"(dst), "l"(src));
}
#define CP_COMMIT() asm volatile("cp.async.commit_group;" ::: "memory")
#define CP_WAIT1()  asm volatile("cp.async.wait_group 1;" ::: "memory")
#define CP_WAIT0()  asm volatile("cp.async.wait_group 0;" ::: "memory")

// bf16 split helpers
__device__ __forceinline__ uint32_t pack2(float a, float b, float& ra, float& rb) {
    __nv_bfloat16 ha = __float2bfloat16(a);
    __nv_bfloat16 hb = __float2bfloat16(b);
    ra = a - __bfloat162float(ha);
    rb = b - __bfloat162float(hb);
    return (uint32_t)__bfloat16_as_ushort(ha) |
           ((uint32_t)__bfloat16_as_ushort(hb) << 16);
}
__device__ __forceinline__ uint32_t pack2lo(float a, float b) {
    return (uint32_t)__bfloat16_as_ushort(__float2bfloat16(a)) |
           ((uint32_t)__bfloat16_as_ushort(__float2bfloat16(b)) << 16);
}

// ----------------------------------------------------------------------------
// Weight transpose + bf16 hi/lo split (also zeroes cnt/cur counters)
// WT[slot][n][k] = W_slot[k][n]
// ----------------------------------------------------------------------------
__global__ void k_wsplit_zero(const float* __restrict__ pW1,
                              const float* __restrict__ pW2,
                              const float* __restrict__ eW0,
                              const float* __restrict__ eW1) {
    int idx = blockIdx.x * blockDim.x + threadIdx.x;
    if (idx < NTOT) { g_cnt[idx] = 0; g_cur[idx] = 0; }
    if (idx >= 4 * HDIM * HDIM) return;
    int slot = idx >> 18;
    int rem = idx & 0x3FFFF;
    int n = rem >> 9;
    int k = rem & 511;
    float w;
    if (slot == 0)      w = pW1[k * HDIM + n];
    else if (slot == 1) w = pW2[k * HDIM + n];
    else if (slot == 2) w = eW0[(3 + k) * HDIM + n];
    else                w = eW1[k * HDIM + n];
    __nv_bfloat16 hi = __float2bfloat16(w);
    __nv_bfloat16 lo = __float2bfloat16(w - __bfloat162float(hi));
    g_WThi[idx] = hi;
    g_WTlo[idx] = lo;
}

__global__ void k_count(const int* __restrict__ col, int E) {
    for (int e = blockIdx.x * blockDim.x + threadIdx.x; e < E;
         e += gridDim.x * blockDim.x)
        atomicAdd(&g_cnt[col[e]], 1);
}
__global__ void k_dinv() {
    int i = blockIdx.x * blockDim.x + threadIdx.x;
    if (i < NTOT) g_dinv[i] = rsqrtf((float)(g_cnt[i] + 1));
}
__global__ void k_fillpad(const int* __restrict__ row,
                          const int* __restrict__ col, int E) {
    for (int e = blockIdx.x * blockDim.x + threadIdx.x; e < E;
         e += gridDim.x * blockDim.x) {
        int c = col[e];
        int r = row[e];
        int p = atomicAdd(&g_cur[c], 1);
        if (p < DEGCAP)
            g_edgeP[(size_t)c * DEGCAP + p] =
                make_int2(r, __float_as_int(g_dinv[r] * g_dinv[c]));
    }
}

// ----------------------------------------------------------------------------
// Fused: width-6 aggregation (from raw x+sdf) + [n,6]@[6,512] + b + relu
// -> bf16 hi/lo.  Block = 8 rows x 512 cols.
// ----------------------------------------------------------------------------
__device__ __forceinline__ float feat6(const float* x, const float* sdf,
                                       int i, int j) {
    return (j < 5) ? x[i * 5 + j] : sdf[i % NFINE];
}

__global__ __launch_bounds__(256) void gemm6agg(
    const float* __restrict__ x, const float* __restrict__ sdf,
    const float* __restrict__ W0, const float* __restrict__ b0,
    __nv_bfloat16* __restrict__ Hhi, __nv_bfloat16* __restrict__ Hlo) {
    __shared__ float sW[6 * HDIM];
    __shared__ float sb[HDIM];
    __shared__ float sa[8][6];
    int tid = threadIdx.x;
    for (int i = tid; i < 6 * HDIM; i += 256) sW[i] = W0[i];
    for (int i = tid; i < HDIM; i += 256) sb[i] = b0[i];
    int row0 = blockIdx.x * 8;
    if (tid < 48) {
        int r = tid / 6, j = tid % 6;
        int c = row0 + r;
        float dc = g_dinv[c];
        float acc = dc * dc * feat6(x, sdf, c, j);
        int cnt = min(g_cnt[c], DEGCAP);
        const int2* ep = g_edgeP + (size_t)c * DEGCAP;
        for (int e = 0; e < cnt; e++) {
            int2 ed = ep[e];
            acc += __int_as_float(ed.y) * feat6(x, sdf, ed.x, j);
        }
        sa[r][j] = acc;
    }
    __syncthreads();
    #pragma unroll
    for (int k = 0; k < 16; k++) {
        int ii = tid + k * 256;          // 0..4095
        int r = ii >> 9;
        int j = ii & 511;
        float v = sb[j];
        #pragma unroll
        for (int kk = 0; kk < 6; kk++) v += sa[r][kk] * sW[kk * HDIM + j];
        v = fmaxf(v, 0.f);
        size_t idx = ((size_t)(row0 + r) << 9) + j;
        __nv_bfloat16 hi = __float2bfloat16(v);
        Hhi[idx] = hi;
        Hlo[idx] = __float2bfloat16(v - __bfloat162float(hi));
    }
}

// ----------------------------------------------------------------------------
// Narrow aggregation (width 3), padded edges
// ----------------------------------------------------------------------------
__global__ void agg3(const float* __restrict__ X, float* __restrict__ Y,
                     const float* __restrict__ bias) {
    int c = blockIdx.x * blockDim.x + threadIdx.x;
    if (c >= NTOT) return;
    float dc = g_dinv[c];
    float w0 = dc * dc;
    float a0 = w0 * X[c * 3 + 0];
    float a1 = w0 * X[c * 3 + 1];
    float a2 = w0 * X[c * 3 + 2];
    int cnt = min(g_cnt[c], DEGCAP);
    const int2* ep = g_edgeP + (size_t)c * DEGCAP;
    for (int e = 0; e < cnt; e++) {
        int2 ed = ep[e];
        float w = __int_as_float(ed.y);
        a0 += w * X[ed.x * 3 + 0];
        a1 += w * X[ed.x * 3 + 1];
        a2 += w * X[ed.x * 3 + 2];
    }
    Y[c * 3 + 0] = a0 + bias[0];
    Y[c * 3 + 1] = a1 + bias[1];
    Y[c * 3 + 2] = a2 + bias[2];
}

// ----------------------------------------------------------------------------
// Wide aggregation (512, fp32 in) + bias + relu + bf16 hi/lo split out.
// WARP-PER-NODE: 256-thread block = 8 nodes; each lane owns 4 float4 chunks
// (lane, lane+32, lane+64, lane+96) -> 4 independent gathers per edge, x2
// edge unroll = 8 loads in flight per lane. Edge list read is warp-uniform.
// ----------------------------------------------------------------------------
__global__ __launch_bounds__(256) void agg512(
    const float4* __restrict__ X,
    __nv_bfloat16* __restrict__ Yhi, __nv_bfloat16* __restrict__ Ylo,
    const float4* __restrict__ bias) {
    int warp = threadIdx.x >> 5;
    int lane = threadIdx.x & 31;
    int c = blockIdx.x * 8 + warp;
    float dc = g_dinv[c];
    float ws = dc * dc;
    const float4* Xc = X + (size_t)c * 128;
    float4 acc[4], acc2[4];
    #pragma unroll
    for (int q = 0; q < 4; q++) {
        float4 v = Xc[lane + 32 * q];
        acc[q]  = make_float4(v.x * ws, v.y * ws, v.z * ws, v.w * ws);
        acc2[q] = make_float4(0.f, 0.f, 0.f, 0.f);
    }
    int cnt = min(g_cnt[c], DEGCAP);
    const int2* ep = g_edgeP + (size_t)c * DEGCAP;
    int e = 0;
    for (; e + 2 <= cnt; e += 2) {
        int2 ea = ep[e];
        int2 eb = ep[e + 1];
        float wa = __int_as_float(ea.y);
        float wb = __int_as_float(eb.y);
        const float4* Xa = X + (size_t)ea.x * 128;
        const float4* Xb = X + (size_t)eb.x * 128;
        #pragma unroll
        for (int q = 0; q < 4; q++) {
            float4 ua = Xa[lane + 32 * q];
            float4 ub = Xb[lane + 32 * q];
            acc[q].x  += wa * ua.x; acc[q].y  += wa * ua.y;
            acc[q].z  += wa * ua.z; acc[q].w  += wa * ua.w;
            acc2[q].x += wb * ub.x; acc2[q].y += wb * ub.y;
            acc2[q].z += wb * ub.z; acc2[q].w += wb * ub.w;
        }
    }
    if (e < cnt) {
        int2 ea = ep[e];
        float wa = __int_as_float(ea.y);
        const float4* Xa = X + (size_t)ea.x * 128;
        #pragma unroll
        for (int q = 0; q < 4; q++) {
            float4 ua = Xa[lane + 32 * q];
            acc[q].x += wa * ua.x; acc[q].y += wa * ua.y;
            acc[q].z += wa * ua.z; acc[q].w += wa * ua.w;
        }
    }
    #pragma unroll
    for (int q = 0; q < 4; q++) {
        int t = lane + 32 * q;
        float4 b = bias[t];
        float vx = fmaxf(acc[q].x + acc2[q].x + b.x, 0.f);
        float vy = fmaxf(acc[q].y + acc2[q].y + b.y, 0.f);
        float vz = fmaxf(acc[q].z + acc2[q].z + b.z, 0.f);
        float vw = fmaxf(acc[q].w + acc2[q].w + b.w, 0.f);
        float rx, ry, rz, rw;
        uint2 hv, lv;
        hv.x = pack2(vx, vy, rx, ry);
        hv.y = pack2(vz, vw, rz, rw);
        lv.x = pack2lo(rx, ry);
        lv.y = pack2lo(rz, rw);
        ((uint2*)Yhi)[(size_t)c * 128 + t] = hv;
        ((uint2*)Ylo)[(size_t)c * 128 + t] = lv;
    }
}

// ----------------------------------------------------------------------------
// GEMM [n,512] @ [512,3] from bf16 hi/lo input, warp per node
// ----------------------------------------------------------------------------
__global__ __launch_bounds__(256) void gemm_out3(
    const __nv_bfloat16* __restrict__ Hhi, const __nv_bfloat16* __restrict__ Hlo,
    const float* __restrict__ W2, float* __restrict__ T3) {
    __shared__ float sW[HDIM * 3];
    int tid = threadIdx.x;
    for (int i = tid; i < HDIM * 3; i += 256) sW[i] = W2[i];
    __syncthreads();
    int warp = tid >> 5, lane = tid & 31;
    for (int node = blockIdx.x * 8 + warp; node < NTOT; node += gridDim.x * 8) {
        const __nv_bfloat16* hp = Hhi + (size_t)node * HDIM;
        const __nv_bfloat16* lp = Hlo + (size_t)node * HDIM;
        float s0 = 0.f, s1 = 0.f, s2 = 0.f;
        for (int k = lane; k < HDIM; k += 32) {
            float h = __bfloat162float(hp[k]) + __bfloat162float(lp[k]);
            s0 += h * sW[k * 3 + 0];
            s1 += h * sW[k * 3 + 1];
            s2 += h * sW[k * 3 + 2];
        }
        #pragma unroll
        for (int o = 16; o; o >>= 1) {
            s0 += __shfl_xor_sync(0xFFFFFFFFu, s0, o);
            s1 += __shfl_xor_sync(0xFFFFFFFFu, s1, o);
            s2 += __shfl_xor_sync(0xFFFFFFFFu, s2, o);
        }
        if (lane == 0) {
            T3[node * 3 + 0] = s0;
            T3[node * 3 + 1] = s1;
            T3[node * 3 + 2] = s2;
        }
    }
}

// ----------------------------------------------------------------------------
// HMMA GEMM: T[80000,512] = (Ahi+Alo)[80000,512] @ (WThi+WTlo)^T  (WT is [N][K])
// bf16x3 split: Ahi*Bhi + Ahi*Blo + Alo*Bhi, fp32 accumulate.
// BM=128, BN=128, BK=32. 8 warps (4m x 2n), m16n8k16 frags.
// 3-STAGE cp.async ring (3 x 32KB = 96KB/CTA; still 2 CTAs/SM = 192KB):
// each load has ~2 compute iterations to land, hiding L2/DRAM latency that
// the 2-stage version exposed at every WAIT. Tile/epilogue unchanged (R9).
// Optional fused T += y3[n,3] @ W3[3,512].
// ----------------------------------------------------------------------------
#define HG_STAGE 32768
#define HG_SMEM  98304

__global__ __launch_bounds__(256, 2) void hgemm(
    const __nv_bfloat16* __restrict__ Ahi, const __nv_bfloat16* __restrict__ Alo,
    const __nv_bfloat16* __restrict__ Bhi, const __nv_bfloat16* __restrict__ Blo,
    float* __restrict__ T,
    const float* __restrict__ y3, const float* __restrict__ W3) {
    extern __shared__ __align__(1024) char sm[];
    uint32_t smb = smem_u32(sm);
    const int tid = threadIdx.x;
    const int lane = tid & 31;
    const int wid = tid >> 5;
    const int warp_m = wid & 3;       // 0..3 -> 32 rows each
    const int warp_n = wid >> 2;      // 0..1 -> 64 cols each
    const int rowBase = blockIdx.y * 128;
    const int colBase = blockIdx.x * 128;

    float acc[2][8][4];
    #pragma unroll
    for (int a = 0; a < 2; a++)
        #pragma unroll
        for (int b = 0; b < 8; b++)
            #pragma unroll
            for (int c = 0; c < 4; c++) acc[a][b][c] = 0.f;

    // cp.async tile loader: 2048 16B chunks (A: 1024, B: 1024), 8 per thread
    auto load_tile = [&](int buf, int kc) {
        #pragma unroll
        for (int t = 0; t < 8; t++) {
            int ci = tid + t * 256;
            int tile = ci >> 10;              // 0 = A, 1 = B
            int r = (ci >> 3) & 127;
            int c = ci & 7;                   // 0-3 hi, 4-7 lo
            uint32_t dst = smb + buf * HG_STAGE + tile * 16384 + r * 128 +
                           (((c ^ (r & 7)) & 7) << 4);
            const __nv_bfloat16* gp;
            if (tile == 0)
                gp = ((c < 4) ? Ahi : Alo) +
                     (((size_t)(rowBase + r)) << 9) + kc * 32 + (c & 3) * 8;
            else
                gp = ((c < 4) ? Bhi : Blo) +
                     (((size_t)(colBase + r)) << 9) + kc * 32 + (c & 3) * 8;
            cp_async16(dst, gp);
        }
    };

    load_tile(0, 0);
    CP_COMMIT();
    load_tile(1, 1);
    CP_COMMIT();

    // ldmatrix per-thread address components
    const int rA = lane & 15;                 // row within m16 tile
    const int cAsel = lane >> 4;              // k-chunk select (0/1)
    const int nB = (lane & 7) | ((lane & 16) >> 1);  // n within 16-row group
    const int cBsel = (lane >> 3) & 1;

    for (int kc = 0; kc < 16; kc++) {
        if (kc == 15) { CP_WAIT0(); } else { CP_WAIT1(); }   // load kc landed
        __syncthreads();                                     // all done w/ kc-1
        if (kc + 2 < 16) {
            load_tile((kc + 2) % 3, kc + 2);                 // slot of kc-1
            CP_COMMIT();
        }

        const uint32_t aBase = smb + (kc % 3) * HG_STAGE;
        const uint32_t bBase = aBase + 16384;

        #pragma unroll
        for (int ks = 0; ks < 2; ks++) {
            uint32_t ah[2][4], al[2][4];
            #pragma unroll
            for (int mt = 0; mt < 2; mt++) {
                int row = warp_m * 32 + mt * 16 + rA;
                int r7 = row & 7;
                int ch = ks * 2 + cAsel;
                ldsm4(ah[mt], aBase + row * 128 + (((ch ^ r7) & 7) << 4));
                ldsm4(al[mt], aBase + row * 128 + ((((ch + 4) ^ r7) & 7) << 4));
            }
            #pragma unroll
            for (int g = 0; g < 4; g++) {
                int n = warp_n * 64 + g * 16 + nB;
                int n7 = n & 7;
                int ch = ks * 2 + cBsel;
                uint32_t bh[4], bl[4];
                ldsm4(bh, bBase + n * 128 + (((ch ^ n7) & 7) << 4));
                ldsm4(bl, bBase + n * 128 + ((((ch + 4) ^ n7) & 7) << 4));
                #pragma unroll
                for (int mt = 0; mt < 2; mt++) {
                    mma16816(acc[mt][2 * g],     ah[mt], bh[0], bh[1]);
                    mma16816(acc[mt][2 * g],     ah[mt], bl[0], bl[1]);
                    mma16816(acc[mt][2 * g],     al[mt], bh[0], bh[1]);
                    mma16816(acc[mt][2 * g + 1], ah[mt], bh[2], bh[3]);
                    mma16816(acc[mt][2 * g + 1], ah[mt], bl[2], bl[3]);
                    mma16816(acc[mt][2 * g + 1], al[mt], bh[2], bh[3]);
                }
            }
        }
    }
    __syncthreads();

    // Optional y3 @ W3[3,512] fusion: stage W3 cols into (now free) smem
    float* sW3 = (float*)sm;
    if (y3) {
        for (int i = tid; i < 384; i += 256)
            sW3[i] = W3[(i >> 7) * HDIM + colBase + (i & 127)];
        __syncthreads();
    }

    const int tr = lane >> 2;       // 0..7
    const int tc = (lane & 3) * 2;
    #pragma unroll
    for (int mt = 0; mt < 2; mt++) {
        #pragma unroll
        for (int h = 0; h < 2; h++) {
            int row = rowBase + warp_m * 32 + mt * 16 + tr + h * 8;
            float y0 = 0.f, y1 = 0.f, y2 = 0.f;
            if (y3) {
                y0 = y3[row * 3 + 0];
                y1 = y3[row * 3 + 1];
                y2 = y3[row * 3 + 2];
            }
            float* Trow = T + ((size_t)row << 9) + colBase;
            #pragma unroll
            for (int nt = 0; nt < 8; nt++) {
                int col = warp_n * 64 + nt * 8 + tc;
                float v0 = acc[mt][nt][h * 2 + 0];
                float v1 = acc[mt][nt][h * 2 + 1];
                if (y3) {
                    v0 += y0 * sW3[col] + y1 * sW3[128 + col] + y2 * sW3[256 + col];
                    v1 += y0 * sW3[col + 1] + y1 * sW3[128 + col + 1] +
                          y2 * sW3[256 + col + 1];
                }
                *(float2*)(Trow + col) = make_float2(v0, v1);
            }
        }
    }
}

// ----------------------------------------------------------------------------
// KNN interpolate
// ----------------------------------------------------------------------------
__global__ __launch_bounds__(128) void knn_kernel(
    const float* __restrict__ x, const float* __restrict__ cx,
    const float* __restrict__ cy, float* __restrict__ y3) {
    __shared__ float s[NCOARSE * 2];
    int tid = threadIdx.x;
    for (int i = tid; i < NCOARSE * 2; i += blockDim.x) s[i] = cx[i];
    __syncthreads();
    int f = blockIdx.x * blockDim.x + tid;
    if (f >= NTOT) return;
    float fx0 = x[f * 5 + 0];
    float fx1 = x[f * 5 + 1];
    float d0 = 3.4e38f, d1 = 3.4e38f, d2 = 3.4e38f;
    int i0 = 0, i1 = 0, i2 = 0;
    for (int c = 0; c < NCOARSE; c++) {
        float ddx = fx0 - s[2 * c];
        float ddy = fx1 - s[2 * c + 1];
        float d = ddx * ddx + ddy * ddy;
        if (d < d2) {
            if (d < d1) {
                if (d < d0) {
                    d2 = d1; i2 = i1; d1 = d0; i1 = i0; d0 = d; i0 = c;
                } else {
                    d2 = d1; i2 = i1; d1 = d; i1 = c;
                }
            } else {
                d2 = d; i2 = c;
            }
        }
    }
    float w0 = 1.f / fmaxf(d0, 1e-16f);
    float w1 = 1.f / fmaxf(d1, 1e-16f);
    float w2 = 1.f / fmaxf(d2, 1e-16f);
    float ws = w0 + w1 + w2;
    int b = f / NFINE;
    const float* c0 = cy + (size_t)(b * NCOARSE + i0) * 3;
    const float* c1 = cy + (size_t)(b * NCOARSE + i1) * 3;
    const float* c2 = cy + (size_t)(b * NCOARSE + i2) * 3;
    #pragma unroll
    for (int j = 0; j < 3; j++)
        y3[f * 3 + j] = (w0 * c0[j] + w1 * c1[j] + w2 * c2[j]) / ws;
}

// ----------------------------------------------------------------------------
// Launch (serial — R12 showed stream fork is neutral on this workload)
// ----------------------------------------------------------------------------
extern "C" void kernel_launch(void* const* d_in, const int* in_sizes, int n_in,
                              void* d_out, int out_size) {
    const float* x   = (const float*)d_in[0];
    const float* sdf = (const float*)d_in[1];
    const int*   ei  = (const int*)d_in[2];
    const float* cx  = (const float*)d_in[3];
    const float* cy  = (const float*)d_in[4];
    const float* pW0 = (const float*)d_in[5];
    const float* pb0 = (const float*)d_in[6];
    const float* pW1 = (const float*)d_in[7];
    const float* pb1 = (const float*)d_in[8];
    const float* pW2 = (const float*)d_in[9];
    const float* pb2 = (const float*)d_in[10];
    const float* eW0 = (const float*)d_in[11];
    const float* eb0 = (const float*)d_in[12];
    const float* eW1 = (const float*)d_in[13];
    const float* eb1 = (const float*)d_in[14];
    const float* eW2 = (const float*)d_in[15];
    const float* eb2 = (const float*)d_in[16];
    float* out = (float*)d_out;

    int E = in_sizes[2] / 2;
    const int* erow = ei;
    const int* ecol = ei + E;

    cudaFuncSetAttribute(hgemm, cudaFuncAttributeMaxDynamicSharedMemorySize,
                         HG_SMEM);

    void *pHaHi, *pHaLo, *pHbHi, *pHbLo, *pT, *pWThi, *pWTlo;
    void *py3, *pt3;
    cudaGetSymbolAddress(&pHaHi, g_HaHi);
    cudaGetSymbolAddress(&pHaLo, g_HaLo);
    cudaGetSymbolAddress(&pHbHi, g_HbHi);
    cudaGetSymbolAddress(&pHbLo, g_HbLo);
    cudaGetSymbolAddress(&pT,  g_T);
    cudaGetSymbolAddress(&pWThi, g_WThi);
    cudaGetSymbolAddress(&pWTlo, g_WTlo);
    cudaGetSymbolAddress(&py3, g_y3);
    cudaGetSymbolAddress(&pt3, g_t3);

    const __nv_bfloat16* WThi = (const __nv_bfloat16*)pWThi;
    const __nv_bfloat16* WTlo = (const __nv_bfloat16*)pWTlo;
    const int WSZ = HDIM * HDIM;

    // weight split + counter zeroing
    k_wsplit_zero<<<(4 * WSZ + 255) / 256, 256>>>(pW1, pW2, eW0, eW1);
    // graph prep (padded CSR, no scan)
    k_count<<<1024, 256>>>(ecol, E);
    k_dinv<<<(NTOT + 255) / 256, 256>>>();
    k_fillpad<<<1024, 256>>>(erow, ecol, E);
    // pre conv 0 fused (width-6 agg + project + bias + relu + split)
    gemm6agg<<<NTOT / 8, 256>>>(x, sdf, pW0, pb0,
                                (__nv_bfloat16*)pHaHi, (__nv_bfloat16*)pHaLo);

    dim3 gg(4, 625);
    // pre conv 1
    hgemm<<<gg, 256, HG_SMEM>>>((__nv_bfloat16*)pHaHi, (__nv_bfloat16*)pHaLo,
                                WThi + 0 * WSZ, WTlo + 0 * WSZ,
                                (float*)pT, nullptr, nullptr);
    agg512<<<NTOT / 8, 256>>>((const float4*)pT, (__nv_bfloat16*)pHbHi,
                              (__nv_bfloat16*)pHbLo, (const float4*)pb1);
    // pre conv 2
    hgemm<<<gg, 256, HG_SMEM>>>((__nv_bfloat16*)pHbHi, (__nv_bfloat16*)pHbLo,
                                WThi + 1 * WSZ, WTlo + 1 * WSZ,
                                (float*)pT, nullptr, nullptr);
    agg512<<<NTOT / 8, 256>>>((const float4*)pT, (__nv_bfloat16*)pHaHi,
                              (__nv_bfloat16*)pHaLo, (const float4*)pb2);
    // KNN interpolate coarse solution onto fine nodes
    knn_kernel<<<(NTOT + 127) / 128, 128>>>(x, cx, cy, (float*)py3);
    // end conv 0 (concat fused: T = Ha@eW0[3:] + y3@eW0[0:3])
    hgemm<<<gg, 256, HG_SMEM>>>((__nv_bfloat16*)pHaHi, (__nv_bfloat16*)pHaLo,
                                WThi + 2 * WSZ, WTlo + 2 * WSZ,
                                (float*)pT, (float*)py3, eW0);
    agg512<<<NTOT / 8, 256>>>((const float4*)pT, (__nv_bfloat16*)pHbHi,
                              (__nv_bfloat16*)pHbLo, (const float4*)eb0);
    // end conv 1
    hgemm<<<gg, 256, HG_SMEM>>>((__nv_bfloat16*)pHbHi, (__nv_bfloat16*)pHbLo,
                                WThi + 3 * WSZ, WTlo + 3 * WSZ,
                                (float*)pT, nullptr, nullptr);
    agg512<<<NTOT / 8, 256>>>((const float4*)pT, (__nv_bfloat16*)pHaHi,
                              (__nv_bfloat16*)pHaLo, (const float4*)eb1);
    // end conv 2 (project to 3, aggregate width 3 + bias, no relu)
    gemm_out3<<<2000, 256>>>((__nv_bfloat16*)pHaHi, (__nv_bfloat16*)pHaLo,
                             eW2, (float*)pt3);
    agg3<<<(NTOT + 255) / 256, 256>>>((float*)pt3, out, eb2);
}

// round 14
// speedup vs baseline: 1.0342x; 1.0342x over previous
#include <cuda_runtime.h>
#include <cuda_bf16.h>
#include <cstdint>

// Problem constants (fixed by the dataset)
#define NTOT    80000      // B * NF
#define NFINE   20000
#define NBATCH  4
#define NCOARSE 2000
#define HDIM    512
#define DEGCAP  32         // padded CSR slot size (in-degree ~ Poisson(6))

// ----------------------------------------------------------------------------
// Scratch (device globals; no allocations allowed)
// ----------------------------------------------------------------------------
__device__ __nv_bfloat16 g_HaHi[(size_t)NTOT * HDIM];
__device__ __nv_bfloat16 g_HaLo[(size_t)NTOT * HDIM];
__device__ __nv_bfloat16 g_HbHi[(size_t)NTOT * HDIM];
__device__ __nv_bfloat16 g_HbLo[(size_t)NTOT * HDIM];
__device__ float g_T [(size_t)NTOT * HDIM];
__device__ __nv_bfloat16 g_WThi[4 * HDIM * HDIM];  // transposed weights [slot][n][k]
__device__ __nv_bfloat16 g_WTlo[4 * HDIM * HDIM];
__device__ float g_y3[(size_t)NTOT * 3];
__device__ float g_t3[(size_t)NTOT * 3];
__device__ float g_dinv[NTOT];
__device__ int   g_cnt[NTOT];
__device__ int   g_cur[NTOT];
__device__ int2  g_edgeP[(size_t)NTOT * DEGCAP];   // padded: {src, bitcast(w)}

// ----------------------------------------------------------------------------
// Warp MMA helpers (plain sm_100-compatible PTX: ldmatrix / mma.sync / cp.async)
// ----------------------------------------------------------------------------
__device__ __forceinline__ uint32_t smem_u32(const void* p) {
    uint32_t a;
    asm("{ .reg .u64 t; cvta.to.shared.u64 t, %1; cvt.u32.u64 %0, t; }"
        : "=r"(a) : "l"(p));
    return a;
}
__device__ __forceinline__ void ldsm4(uint32_t* d, uint32_t addr) {
    asm volatile("ldmatrix.sync.aligned.m8n8.x4.shared.b16 {%0,%1,%2,%3}, [%4];"
        : "=r"(d[0]), "=r"(d[1]), "=r"(d[2]), "=r"(d[3]) : "r"(addr));
}
__device__ __forceinline__ void mma16816(float* c, const uint32_t* a,
                                         uint32_t b0, uint32_t b1) {
    asm volatile(
        "mma.sync.aligned.m16n8k16.row.col.f32.bf16.bf16.f32 "
        "{%0,%1,%2,%3}, {%4,%5,%6,%7}, {%8,%9}, {%0,%1,%2,%3};"
        : "+f"(c[0]), "+f"(c[1]), "+f"(c[2]), "+f"(c[3])
        : "r"(a[0]), "r"(a[1]), "r"(a[2]), "r"(a[3]), "r"(b0), "r"(b1));
}
__device__ __forceinline__ void cp_async16(uint32_t dst, const void* src) {
    asm volatile("cp.async.cg.shared.global [%0], [%1], 16;"
        :: "r"(dst), "l"(src));
}
#define CP_COMMIT() asm volatile("cp.async.commit_group;" ::: "memory")
#define CP_WAIT1()  asm volatile("cp.async.wait_group 1;" ::: "memory")
#define CP_WAIT0()  asm volatile("cp.async.wait_group 0;" ::: "memory")

// bf16 split helpers
__device__ __forceinline__ uint32_t pack2(float a, float b, float& ra, float& rb) {
    __nv_bfloat16 ha = __float2bfloat16(a);
    __nv_bfloat16 hb = __float2bfloat16(b);
    ra = a - __bfloat162float(ha);
    rb = b - __bfloat162float(hb);
    return (uint32_t)__bfloat16_as_ushort(ha) |
           ((uint32_t)__bfloat16_as_ushort(hb) << 16);
}
__device__ __forceinline__ uint32_t pack2lo(float a, float b) {
    return (uint32_t)__bfloat16_as_ushort(__float2bfloat16(a)) |
           ((uint32_t)__bfloat16_as_ushort(__float2bfloat16(b)) << 16);
}

// ----------------------------------------------------------------------------
// Weight transpose + bf16 hi/lo split (also zeroes cnt/cur counters)
// WT[slot][n][k] = W_slot[k][n]
// ----------------------------------------------------------------------------
__global__ void k_wsplit_zero(const float* __restrict__ pW1,
                              const float* __restrict__ pW2,
                              const float* __restrict__ eW0,
                              const float* __restrict__ eW1) {
    int idx = blockIdx.x * blockDim.x + threadIdx.x;
    if (idx < NTOT) { g_cnt[idx] = 0; g_cur[idx] = 0; }
    if (idx >= 4 * HDIM * HDIM) return;
    int slot = idx >> 18;
    int rem = idx & 0x3FFFF;
    int n = rem >> 9;
    int k = rem & 511;
    float w;
    if (slot == 0)      w = pW1[k * HDIM + n];
    else if (slot == 1) w = pW2[k * HDIM + n];
    else if (slot == 2) w = eW0[(3 + k) * HDIM + n];
    else                w = eW1[k * HDIM + n];
    __nv_bfloat16 hi = __float2bfloat16(w);
    __nv_bfloat16 lo = __float2bfloat16(w - __bfloat162float(hi));
    g_WThi[idx] = hi;
    g_WTlo[idx] = lo;
}

__global__ void k_count(const int* __restrict__ col, int E) {
    for (int e = blockIdx.x * blockDim.x + threadIdx.x; e < E;
         e += gridDim.x * blockDim.x)
        atomicAdd(&g_cnt[col[e]], 1);
}
__global__ void k_dinv() {
    int i = blockIdx.x * blockDim.x + threadIdx.x;
    if (i < NTOT) g_dinv[i] = rsqrtf((float)(g_cnt[i] + 1));
}
__global__ void k_fillpad(const int* __restrict__ row,
                          const int* __restrict__ col, int E) {
    for (int e = blockIdx.x * blockDim.x + threadIdx.x; e < E;
         e += gridDim.x * blockDim.x) {
        int c = col[e];
        int r = row[e];
        int p = atomicAdd(&g_cur[c], 1);
        if (p < DEGCAP)
            g_edgeP[(size_t)c * DEGCAP + p] =
                make_int2(r, __float_as_int(g_dinv[r] * g_dinv[c]));
    }
}

// ----------------------------------------------------------------------------
// Fused: width-6 aggregation (from raw x+sdf) + [n,6]@[6,512] + b + relu
// -> bf16 hi/lo.  Block = 8 rows x 512 cols.
// ----------------------------------------------------------------------------
__device__ __forceinline__ float feat6(const float* x, const float* sdf,
                                       int i, int j) {
    return (j < 5) ? x[i * 5 + j] : sdf[i % NFINE];
}

__global__ __launch_bounds__(256) void gemm6agg(
    const float* __restrict__ x, const float* __restrict__ sdf,
    const float* __restrict__ W0, const float* __restrict__ b0,
    __nv_bfloat16* __restrict__ Hhi, __nv_bfloat16* __restrict__ Hlo) {
    __shared__ float sW[6 * HDIM];
    __shared__ float sb[HDIM];
    __shared__ float sa[8][6];
    int tid = threadIdx.x;
    for (int i = tid; i < 6 * HDIM; i += 256) sW[i] = W0[i];
    for (int i = tid; i < HDIM; i += 256) sb[i] = b0[i];
    int row0 = blockIdx.x * 8;
    if (tid < 48) {
        int r = tid / 6, j = tid % 6;
        int c = row0 + r;
        float dc = g_dinv[c];
        float acc = dc * dc * feat6(x, sdf, c, j);
        int cnt = min(g_cnt[c], DEGCAP);
        const int2* ep = g_edgeP + (size_t)c * DEGCAP;
        for (int e = 0; e < cnt; e++) {
            int2 ed = ep[e];
            acc += __int_as_float(ed.y) * feat6(x, sdf, ed.x, j);
        }
        sa[r][j] = acc;
    }
    __syncthreads();
    #pragma unroll
    for (int k = 0; k < 16; k++) {
        int ii = tid + k * 256;          // 0..4095
        int r = ii >> 9;
        int j = ii & 511;
        float v = sb[j];
        #pragma unroll
        for (int kk = 0; kk < 6; kk++) v += sa[r][kk] * sW[kk * HDIM + j];
        v = fmaxf(v, 0.f);
        size_t idx = ((size_t)(row0 + r) << 9) + j;
        __nv_bfloat16 hi = __float2bfloat16(v);
        Hhi[idx] = hi;
        Hlo[idx] = __float2bfloat16(v - __bfloat162float(hi));
    }
}

// ----------------------------------------------------------------------------
// Narrow aggregation (width 3), padded edges
// ----------------------------------------------------------------------------
__global__ void agg3(const float* __restrict__ X, float* __restrict__ Y,
                     const float* __restrict__ bias) {
    int c = blockIdx.x * blockDim.x + threadIdx.x;
    if (c >= NTOT) return;
    float dc = g_dinv[c];
    float w0 = dc * dc;
    float a0 = w0 * X[c * 3 + 0];
    float a1 = w0 * X[c * 3 + 1];
    float a2 = w0 * X[c * 3 + 2];
    int cnt = min(g_cnt[c], DEGCAP);
    const int2* ep = g_edgeP + (size_t)c * DEGCAP;
    for (int e = 0; e < cnt; e++) {
        int2 ed = ep[e];
        float w = __int_as_float(ed.y);
        a0 += w * X[ed.x * 3 + 0];
        a1 += w * X[ed.x * 3 + 1];
        a2 += w * X[ed.x * 3 + 2];
    }
    Y[c * 3 + 0] = a0 + bias[0];
    Y[c * 3 + 1] = a1 + bias[1];
    Y[c * 3 + 2] = a2 + bias[2];
}

// ----------------------------------------------------------------------------
// Wide aggregation (512, fp32 in) + bias + relu + bf16 hi/lo split out.
// WARP-PER-NODE: 256-thread block = 8 nodes; each lane owns 4 float4 chunks
// (lane, lane+32, lane+64, lane+96) -> 4 independent gathers per edge, x2
// edge unroll = 8 loads in flight per lane. Edge list read is warp-uniform.
// ----------------------------------------------------------------------------
__global__ __launch_bounds__(256) void agg512(
    const float4* __restrict__ X,
    __nv_bfloat16* __restrict__ Yhi, __nv_bfloat16* __restrict__ Ylo,
    const float4* __restrict__ bias) {
    int warp = threadIdx.x >> 5;
    int lane = threadIdx.x & 31;
    int c = blockIdx.x * 8 + warp;
    float dc = g_dinv[c];
    float ws = dc * dc;
    const float4* Xc = X + (size_t)c * 128;
    float4 acc[4], acc2[4];
    #pragma unroll
    for (int q = 0; q < 4; q++) {
        float4 v = Xc[lane + 32 * q];
        acc[q]  = make_float4(v.x * ws, v.y * ws, v.z * ws, v.w * ws);
        acc2[q] = make_float4(0.f, 0.f, 0.f, 0.f);
    }
    int cnt = min(g_cnt[c], DEGCAP);
    const int2* ep = g_edgeP + (size_t)c * DEGCAP;
    int e = 0;
    for (; e + 2 <= cnt; e += 2) {
        int2 ea = ep[e];
        int2 eb = ep[e + 1];
        float wa = __int_as_float(ea.y);
        float wb = __int_as_float(eb.y);
        const float4* Xa = X + (size_t)ea.x * 128;
        const float4* Xb = X + (size_t)eb.x * 128;
        #pragma unroll
        for (int q = 0; q < 4; q++) {
            float4 ua = Xa[lane + 32 * q];
            float4 ub = Xb[lane + 32 * q];
            acc[q].x  += wa * ua.x; acc[q].y  += wa * ua.y;
            acc[q].z  += wa * ua.z; acc[q].w  += wa * ua.w;
            acc2[q].x += wb * ub.x; acc2[q].y += wb * ub.y;
            acc2[q].z += wb * ub.z; acc2[q].w += wb * ub.w;
        }
    }
    if (e < cnt) {
        int2 ea = ep[e];
        float wa = __int_as_float(ea.y);
        const float4* Xa = X + (size_t)ea.x * 128;
        #pragma unroll
        for (int q = 0; q < 4; q++) {
            float4 ua = Xa[lane + 32 * q];
            acc[q].x += wa * ua.x; acc[q].y += wa * ua.y;
            acc[q].z += wa * ua.z; acc[q].w += wa * ua.w;
        }
    }
    #pragma unroll
    for (int q = 0; q < 4; q++) {
        int t = lane + 32 * q;
        float4 b = bias[t];
        float vx = fmaxf(acc[q].x + acc2[q].x + b.x, 0.f);
        float vy = fmaxf(acc[q].y + acc2[q].y + b.y, 0.f);
        float vz = fmaxf(acc[q].z + acc2[q].z + b.z, 0.f);
        float vw = fmaxf(acc[q].w + acc2[q].w + b.w, 0.f);
        float rx, ry, rz, rw;
        uint2 hv, lv;
        hv.x = pack2(vx, vy, rx, ry);
        hv.y = pack2(vz, vw, rz, rw);
        lv.x = pack2lo(rx, ry);
        lv.y = pack2lo(rz, rw);
        ((uint2*)Yhi)[(size_t)c * 128 + t] = hv;
        ((uint2*)Ylo)[(size_t)c * 128 + t] = lv;
    }
}

// ----------------------------------------------------------------------------
// FUSED final aggregation + 512->3 projection (end conv 1 + end conv 2 GEMM):
// t3[c] = relu(Agg(T)[c] + bias) @ W2.  Same warp-per-node gather as agg512;
// epilogue keeps y in registers (exact fp32 — MORE accurate than the bf16
// round-trip it replaces), dots against W2 columns staged as float4 in smem,
// warp-reduces 3 scalars. Eliminates the 328MB Ha write + 328MB re-read.
// ----------------------------------------------------------------------------
__global__ __launch_bounds__(256) void agg512_out3(
    const float4* __restrict__ X, const float4* __restrict__ bias,
    const float* __restrict__ W2, float* __restrict__ T3) {
    __shared__ float4 sW4[3][128];   // sW4[j][t] = W2[(4t+k)*3 + j], k=0..3
    int tid = threadIdx.x;
    for (int i = tid; i < 384; i += 256) {
        int j = i >> 7;
        int t = i & 127;
        sW4[j][t] = make_float4(W2[(4 * t + 0) * 3 + j], W2[(4 * t + 1) * 3 + j],
                                W2[(4 * t + 2) * 3 + j], W2[(4 * t + 3) * 3 + j]);
    }
    __syncthreads();
    int warp = tid >> 5;
    int lane = tid & 31;
    int c = blockIdx.x * 8 + warp;
    float dc = g_dinv[c];
    float ws = dc * dc;
    const float4* Xc = X + (size_t)c * 128;
    float4 acc[4], acc2[4];
    #pragma unroll
    for (int q = 0; q < 4; q++) {
        float4 v = Xc[lane + 32 * q];
        acc[q]  = make_float4(v.x * ws, v.y * ws, v.z * ws, v.w * ws);
        acc2[q] = make_float4(0.f, 0.f, 0.f, 0.f);
    }
    int cnt = min(g_cnt[c], DEGCAP);
    const int2* ep = g_edgeP + (size_t)c * DEGCAP;
    int e = 0;
    for (; e + 2 <= cnt; e += 2) {
        int2 ea = ep[e];
        int2 eb = ep[e + 1];
        float wa = __int_as_float(ea.y);
        float wb = __int_as_float(eb.y);
        const float4* Xa = X + (size_t)ea.x * 128;
        const float4* Xb = X + (size_t)eb.x * 128;
        #pragma unroll
        for (int q = 0; q < 4; q++) {
            float4 ua = Xa[lane + 32 * q];
            float4 ub = Xb[lane + 32 * q];
            acc[q].x  += wa * ua.x; acc[q].y  += wa * ua.y;
            acc[q].z  += wa * ua.z; acc[q].w  += wa * ua.w;
            acc2[q].x += wb * ub.x; acc2[q].y += wb * ub.y;
            acc2[q].z += wb * ub.z; acc2[q].w += wb * ub.w;
        }
    }
    if (e < cnt) {
        int2 ea = ep[e];
        float wa = __int_as_float(ea.y);
        const float4* Xa = X + (size_t)ea.x * 128;
        #pragma unroll
        for (int q = 0; q < 4; q++) {
            float4 ua = Xa[lane + 32 * q];
            acc[q].x += wa * ua.x; acc[q].y += wa * ua.y;
            acc[q].z += wa * ua.z; acc[q].w += wa * ua.w;
        }
    }
    float s0 = 0.f, s1 = 0.f, s2 = 0.f;
    #pragma unroll
    for (int q = 0; q < 4; q++) {
        int t = lane + 32 * q;
        float4 b = bias[t];
        float4 y;
        y.x = fmaxf(acc[q].x + acc2[q].x + b.x, 0.f);
        y.y = fmaxf(acc[q].y + acc2[q].y + b.y, 0.f);
        y.z = fmaxf(acc[q].z + acc2[q].z + b.z, 0.f);
        y.w = fmaxf(acc[q].w + acc2[q].w + b.w, 0.f);
        float4 w0 = sW4[0][t], w1 = sW4[1][t], w2 = sW4[2][t];
        s0 += y.x * w0.x + y.y * w0.y + y.z * w0.z + y.w * w0.w;
        s1 += y.x * w1.x + y.y * w1.y + y.z * w1.z + y.w * w1.w;
        s2 += y.x * w2.x + y.y * w2.y + y.z * w2.z + y.w * w2.w;
    }
    #pragma unroll
    for (int o = 16; o; o >>= 1) {
        s0 += __shfl_xor_sync(0xFFFFFFFFu, s0, o);
        s1 += __shfl_xor_sync(0xFFFFFFFFu, s1, o);
        s2 += __shfl_xor_sync(0xFFFFFFFFu, s2, o);
    }
    if (lane == 0) {
        T3[c * 3 + 0] = s0;
        T3[c * 3 + 1] = s1;
        T3[c * 3 + 2] = s2;
    }
}

// ----------------------------------------------------------------------------
// HMMA GEMM (R9/R11 config — proven local optimum):
// T[80000,512] = (Ahi+Alo)[80000,512] @ (WThi+WTlo)^T  (WT is [N][K])
// bf16x3 split: Ahi*Bhi + Ahi*Blo + Alo*Bhi, fp32 accumulate.
// BM=128, BN=128, BK=32. 8 warps (4m x 2n), m16n8k16 frags.
// Double-buffered cp.async (2 x 32KB). Optional fused T += y3[n,3] @ W3[3,512].
// ----------------------------------------------------------------------------
#define HG_SMEM 65536

__global__ __launch_bounds__(256, 2) void hgemm(
    const __nv_bfloat16* __restrict__ Ahi, const __nv_bfloat16* __restrict__ Alo,
    const __nv_bfloat16* __restrict__ Bhi, const __nv_bfloat16* __restrict__ Blo,
    float* __restrict__ T,
    const float* __restrict__ y3, const float* __restrict__ W3) {
    extern __shared__ __align__(1024) char sm[];
    uint32_t smb = smem_u32(sm);
    const int tid = threadIdx.x;
    const int lane = tid & 31;
    const int wid = tid >> 5;
    const int warp_m = wid & 3;       // 0..3 -> 32 rows each
    const int warp_n = wid >> 2;      // 0..1 -> 64 cols each
    const int rowBase = blockIdx.y * 128;
    const int colBase = blockIdx.x * 128;

    float acc[2][8][4];
    #pragma unroll
    for (int a = 0; a < 2; a++)
        #pragma unroll
        for (int b = 0; b < 8; b++)
            #pragma unroll
            for (int c = 0; c < 4; c++) acc[a][b][c] = 0.f;

    // cp.async tile loader: 2048 16B chunks (A: 1024, B: 1024), 8 per thread
    auto load_tile = [&](int buf, int kc) {
        #pragma unroll
        for (int t = 0; t < 8; t++) {
            int ci = tid + t * 256;
            int tile = ci >> 10;              // 0 = A, 1 = B
            int r = (ci >> 3) & 127;
            int c = ci & 7;                   // 0-3 hi, 4-7 lo
            uint32_t dst = smb + buf * 32768 + tile * 16384 + r * 128 +
                           (((c ^ (r & 7)) & 7) << 4);
            const __nv_bfloat16* gp;
            if (tile == 0)
                gp = ((c < 4) ? Ahi : Alo) +
                     (((size_t)(rowBase + r)) << 9) + kc * 32 + (c & 3) * 8;
            else
                gp = ((c < 4) ? Bhi : Blo) +
                     (((size_t)(colBase + r)) << 9) + kc * 32 + (c & 3) * 8;
            cp_async16(dst, gp);
        }
    };

    load_tile(0, 0);
    CP_COMMIT();

    // ldmatrix per-thread address components
    const int rA = lane & 15;                 // row within m16 tile
    const int cAsel = lane >> 4;              // k-chunk select (0/1)
    const int nB = (lane & 7) | ((lane & 16) >> 1);  // n within 16-row group
    const int cBsel = (lane >> 3) & 1;

    for (int kc = 0; kc < 16; kc++) {
        if (kc < 15) {
            load_tile((kc + 1) & 1, kc + 1);
            CP_COMMIT();
            CP_WAIT1();
        } else {
            CP_WAIT0();
        }
        __syncthreads();

        const uint32_t aBase = smb + (kc & 1) * 32768;
        const uint32_t bBase = aBase + 16384;

        #pragma unroll
        for (int ks = 0; ks < 2; ks++) {
            uint32_t ah[2][4], al[2][4];
            #pragma unroll
            for (int mt = 0; mt < 2; mt++) {
                int row = warp_m * 32 + mt * 16 + rA;
                int r7 = row & 7;
                int ch = ks * 2 + cAsel;
                ldsm4(ah[mt], aBase + row * 128 + (((ch ^ r7) & 7) << 4));
                ldsm4(al[mt], aBase + row * 128 + ((((ch + 4) ^ r7) & 7) << 4));
            }
            #pragma unroll
            for (int g = 0; g < 4; g++) {
                int n = warp_n * 64 + g * 16 + nB;
                int n7 = n & 7;
                int ch = ks * 2 + cBsel;
                uint32_t bh[4], bl[4];
                ldsm4(bh, bBase + n * 128 + (((ch ^ n7) & 7) << 4));
                ldsm4(bl, bBase + n * 128 + ((((ch + 4) ^ n7) & 7) << 4));
                #pragma unroll
                for (int mt = 0; mt < 2; mt++) {
                    mma16816(acc[mt][2 * g],     ah[mt], bh[0], bh[1]);
                    mma16816(acc[mt][2 * g],     ah[mt], bl[0], bl[1]);
                    mma16816(acc[mt][2 * g],     al[mt], bh[0], bh[1]);
                    mma16816(acc[mt][2 * g + 1], ah[mt], bh[2], bh[3]);
                    mma16816(acc[mt][2 * g + 1], ah[mt], bl[2], bl[3]);
                    mma16816(acc[mt][2 * g + 1], al[mt], bh[2], bh[3]);
                }
            }
        }
        __syncthreads();
    }

    // Optional y3 @ W3[3,512] fusion: stage W3 cols into (now free) smem
    float* sW3 = (float*)sm;
    if (y3) {
        for (int i = tid; i < 384; i += 256)
            sW3[i] = W3[(i >> 7) * HDIM + colBase + (i & 127)];
        __syncthreads();
    }

    const int tr = lane >> 2;       // 0..7
    const int tc = (lane & 3) * 2;
    #pragma unroll
    for (int mt = 0; mt < 2; mt++) {
        #pragma unroll
        for (int h = 0; h < 2; h++) {
            int row = rowBase + warp_m * 32 + mt * 16 + tr + h * 8;
            float y0 = 0.f, y1 = 0.f, y2 = 0.f;
            if (y3) {
                y0 = y3[row * 3 + 0];
                y1 = y3[row * 3 + 1];
                y2 = y3[row * 3 + 2];
            }
            float* Trow = T + ((size_t)row << 9) + colBase;
            #pragma unroll
            for (int nt = 0; nt < 8; nt++) {
                int col = warp_n * 64 + nt * 8 + tc;
                float v0 = acc[mt][nt][h * 2 + 0];
                float v1 = acc[mt][nt][h * 2 + 1];
                if (y3) {
                    v0 += y0 * sW3[col] + y1 * sW3[128 + col] + y2 * sW3[256 + col];
                    v1 += y0 * sW3[col + 1] + y1 * sW3[128 + col + 1] +
                          y2 * sW3[256 + col + 1];
                }
                *(float2*)(Trow + col) = make_float2(v0, v1);
            }
        }
    }
}

// ----------------------------------------------------------------------------
// KNN interpolate
// ----------------------------------------------------------------------------
__global__ __launch_bounds__(128) void knn_kernel(
    const float* __restrict__ x, const float* __restrict__ cx,
    const float* __restrict__ cy, float* __restrict__ y3) {
    __shared__ float s[NCOARSE * 2];
    int tid = threadIdx.x;
    for (int i = tid; i < NCOARSE * 2; i += blockDim.x) s[i] = cx[i];
    __syncthreads();
    int f = blockIdx.x * blockDim.x + tid;
    if (f >= NTOT) return;
    float fx0 = x[f * 5 + 0];
    float fx1 = x[f * 5 + 1];
    float d0 = 3.4e38f, d1 = 3.4e38f, d2 = 3.4e38f;
    int i0 = 0, i1 = 0, i2 = 0;
    for (int c = 0; c < NCOARSE; c++) {
        float ddx = fx0 - s[2 * c];
        float ddy = fx1 - s[2 * c + 1];
        float d = ddx * ddx + ddy * ddy;
        if (d < d2) {
            if (d < d1) {
                if (d < d0) {
                    d2 = d1; i2 = i1; d1 = d0; i1 = i0; d0 = d; i0 = c;
                } else {
                    d2 = d1; i2 = i1; d1 = d; i1 = c;
                }
            } else {
                d2 = d; i2 = c;
            }
        }
    }
    float w0 = 1.f / fmaxf(d0, 1e-16f);
    float w1 = 1.f / fmaxf(d1, 1e-16f);
    float w2 = 1.f / fmaxf(d2, 1e-16f);
    float ws = w0 + w1 + w2;
    int b = f / NFINE;
    const float* c0 = cy + (size_t)(b * NCOARSE + i0) * 3;
    const float* c1 = cy + (size_t)(b * NCOARSE + i1) * 3;
    const float* c2 = cy + (size_t)(b * NCOARSE + i2) * 3;
    #pragma unroll
    for (int j = 0; j < 3; j++)
        y3[f * 3 + j] = (w0 * c0[j] + w1 * c1[j] + w2 * c2[j]) / ws;
}

// ----------------------------------------------------------------------------
// Launch
// ----------------------------------------------------------------------------
extern "C" void kernel_launch(void* const* d_in, const int* in_sizes, int n_in,
                              void* d_out, int out_size) {
    const float* x   = (const float*)d_in[0];
    const float* sdf = (const float*)d_in[1];
    const int*   ei  = (const int*)d_in[2];
    const float* cx  = (const float*)d_in[3];
    const float* cy  = (const float*)d_in[4];
    const float* pW0 = (const float*)d_in[5];
    const float* pb0 = (const float*)d_in[6];
    const float* pW1 = (const float*)d_in[7];
    const float* pb1 = (const float*)d_in[8];
    const float* pW2 = (const float*)d_in[9];
    const float* pb2 = (const float*)d_in[10];
    const float* eW0 = (const float*)d_in[11];
    const float* eb0 = (const float*)d_in[12];
    const float* eW1 = (const float*)d_in[13];
    const float* eb1 = (const float*)d_in[14];
    const float* eW2 = (const float*)d_in[15];
    const float* eb2 = (const float*)d_in[16];
    float* out = (float*)d_out;

    int E = in_sizes[2] / 2;
    const int* erow = ei;
    const int* ecol = ei + E;

    cudaFuncSetAttribute(hgemm, cudaFuncAttributeMaxDynamicSharedMemorySize,
                         HG_SMEM);

    void *pHaHi, *pHaLo, *pHbHi, *pHbLo, *pT, *pWThi, *pWTlo;
    void *py3, *pt3;
    cudaGetSymbolAddress(&pHaHi, g_HaHi);
    cudaGetSymbolAddress(&pHaLo, g_HaLo);
    cudaGetSymbolAddress(&pHbHi, g_HbHi);
    cudaGetSymbolAddress(&pHbLo, g_HbLo);
    cudaGetSymbolAddress(&pT,  g_T);
    cudaGetSymbolAddress(&pWThi, g_WThi);
    cudaGetSymbolAddress(&pWTlo, g_WTlo);
    cudaGetSymbolAddress(&py3, g_y3);
    cudaGetSymbolAddress(&pt3, g_t3);

    const __nv_bfloat16* WThi = (const __nv_bfloat16*)pWThi;
    const __nv_bfloat16* WTlo = (const __nv_bfloat16*)pWTlo;
    const int WSZ = HDIM * HDIM;

    // weight split + counter zeroing
    k_wsplit_zero<<<(4 * WSZ + 255) / 256, 256>>>(pW1, pW2, eW0, eW1);
    // graph prep (padded CSR, no scan)
    k_count<<<1024, 256>>>(ecol, E);
    k_dinv<<<(NTOT + 255) / 256, 256>>>();
    k_fillpad<<<1024, 256>>>(erow, ecol, E);
    // pre conv 0 fused (width-6 agg + project + bias + relu + split)
    gemm6agg<<<NTOT / 8, 256>>>(x, sdf, pW0, pb0,
                                (__nv_bfloat16*)pHaHi, (__nv_bfloat16*)pHaLo);

    dim3 gg(4, 625);
    // pre conv 1
    hgemm<<<gg, 256, HG_SMEM>>>((__nv_bfloat16*)pHaHi, (__nv_bfloat16*)pHaLo,
                                WThi + 0 * WSZ, WTlo + 0 * WSZ,
                                (float*)pT, nullptr, nullptr);
    agg512<<<NTOT / 8, 256>>>((const float4*)pT, (__nv_bfloat16*)pHbHi,
                              (__nv_bfloat16*)pHbLo, (const float4*)pb1);
    // pre conv 2
    hgemm<<<gg, 256, HG_SMEM>>>((__nv_bfloat16*)pHbHi, (__nv_bfloat16*)pHbLo,
                                WThi + 1 * WSZ, WTlo + 1 * WSZ,
                                (float*)pT, nullptr, nullptr);
    agg512<<<NTOT / 8, 256>>>((const float4*)pT, (__nv_bfloat16*)pHaHi,
                              (__nv_bfloat16*)pHaLo, (const float4*)pb2);
    // KNN interpolate coarse solution onto fine nodes
    knn_kernel<<<(NTOT + 127) / 128, 128>>>(x, cx, cy, (float*)py3);
    // end conv 0 (concat fused: T = Ha@eW0[3:] + y3@eW0[0:3])
    hgemm<<<gg, 256, HG_SMEM>>>((__nv_bfloat16*)pHaHi, (__nv_bfloat16*)pHaLo,
                                WThi + 2 * WSZ, WTlo + 2 * WSZ,
                                (float*)pT, (float*)py3, eW0);
    agg512<<<NTOT / 8, 256>>>((const float4*)pT, (__nv_bfloat16*)pHbHi,
                              (__nv_bfloat16*)pHbLo, (const float4*)eb0);
    // end conv 1 GEMM, then FUSED agg+relu+projection straight to width 3
    hgemm<<<gg, 256, HG_SMEM>>>((__nv_bfloat16*)pHbHi, (__nv_bfloat16*)pHbLo,
                                WThi + 3 * WSZ, WTlo + 3 * WSZ,
                                (float*)pT, nullptr, nullptr);
    agg512_out3<<<NTOT / 8, 256>>>((const float4*)pT, (const float4*)eb1,
                                   eW2, (float*)pt3);
    // end conv 2 aggregation (width 3 + bias, no relu)
    agg3<<<(NTOT + 255) / 256, 256>>>((float*)pt3, out, eb2);
}